// round 2
// baseline (speedup 1.0000x reference)
#include <cuda_runtime.h>

#define Tz 512
#define Bz 32
#define Iz 256
#define Hz 512
#define Gz 2048          // 4*H
#define TB (Tz*Bz)       // 16384

// -------- scratch (device globals; no runtime allocation) --------
__device__ float g_xt[(size_t)TB * Iz];        // x transposed to [T,B,I]
__device__ float g_xg0[(size_t)TB * Gz];       // fwd-dir input-gate projections
__device__ float g_xg1[(size_t)TB * Gz];       // bwd-dir input-gate projections
__device__ float g_y0[(size_t)TB * 2 * Hz];    // layer-0 output [T,B,2H]
__device__ float g_hbuf[2][2][Hz * Bz];        // [dir][parity][u*32+b]  (k-major!)
__device__ float g_cbuf[2][Bz * Hz];           // [dir][b*H+u]
__device__ unsigned g_barcnt[2];               // per-direction arrival counters

__device__ __forceinline__ float sigf(float x) { return 1.f / (1.f + __expf(-x)); }
__device__ __forceinline__ float tanhf_(float x) { return 2.f / (1.f + __expf(-2.f * x)) - 1.f; }

// -------- transpose x [B,I,T] -> xt [T,B,I] --------
__global__ void transpose_x(const float* __restrict__ x) {
    __shared__ float tile[32][33];
    int b = blockIdx.z, i0 = blockIdx.y * 32, t0 = blockIdx.x * 32;
    int tx = threadIdx.x, ty = threadIdx.y;
#pragma unroll
    for (int r = ty; r < 32; r += 8)
        tile[r][tx] = x[(size_t)b * Iz * Tz + (size_t)(i0 + r) * Tz + t0 + tx];
    __syncthreads();
#pragma unroll
    for (int r = ty; r < 32; r += 8)
        g_xt[(size_t)(t0 + r) * Bz * Iz + (size_t)b * Iz + i0 + tx] = tile[tx][r];
}

// -------- xg = A[M,K] @ W[N,K]^T + (bi + bh), M=16384, N=2048 --------
__global__ __launch_bounds__(256) void gemm_xg(
    const float* __restrict__ A, const float* __restrict__ W,
    const float* __restrict__ bi, const float* __restrict__ bh,
    float* __restrict__ C, int K)
{
    __shared__ float As[16 * 132];
    __shared__ float Bs[16 * 132];
    int tid = threadIdx.x;
    int tx = tid & 15, ty = tid >> 4;
    int n0 = blockIdx.x * 128, m0 = blockIdx.y * 128;
    int lrow = tid >> 2;
    int kq = tid & 3;

    float acc[8][8];
#pragma unroll
    for (int i = 0; i < 8; i++)
#pragma unroll
        for (int j = 0; j < 8; j++) acc[i][j] = 0.f;

    for (int k0 = 0; k0 < K; k0 += 16) {
#pragma unroll
        for (int h = 0; h < 2; h++) {
            int r = lrow + h * 64;
            float4 va = *(const float4*)&A[(size_t)(m0 + r) * K + k0 + kq * 4];
            As[(kq * 4 + 0) * 132 + r] = va.x;
            As[(kq * 4 + 1) * 132 + r] = va.y;
            As[(kq * 4 + 2) * 132 + r] = va.z;
            As[(kq * 4 + 3) * 132 + r] = va.w;
            float4 vb = *(const float4*)&W[(size_t)(n0 + r) * K + k0 + kq * 4];
            Bs[(kq * 4 + 0) * 132 + r] = vb.x;
            Bs[(kq * 4 + 1) * 132 + r] = vb.y;
            Bs[(kq * 4 + 2) * 132 + r] = vb.z;
            Bs[(kq * 4 + 3) * 132 + r] = vb.w;
        }
        __syncthreads();
#pragma unroll
        for (int k = 0; k < 16; k++) {
            float4 a0 = *(const float4*)&As[k * 132 + ty * 8];
            float4 a1 = *(const float4*)&As[k * 132 + ty * 8 + 4];
            float4 b0 = *(const float4*)&Bs[k * 132 + tx * 8];
            float4 b1 = *(const float4*)&Bs[k * 132 + tx * 8 + 4];
            float av[8] = {a0.x, a0.y, a0.z, a0.w, a1.x, a1.y, a1.z, a1.w};
            float bv[8] = {b0.x, b0.y, b0.z, b0.w, b1.x, b1.y, b1.z, b1.w};
#pragma unroll
            for (int i = 0; i < 8; i++)
#pragma unroll
                for (int j = 0; j < 8; j++) acc[i][j] += av[i] * bv[j];
        }
        __syncthreads();
    }
#pragma unroll
    for (int i = 0; i < 8; i++) {
        int m = m0 + ty * 8 + i;
#pragma unroll
        for (int jq = 0; jq < 2; jq++) {
            int n = n0 + tx * 8 + jq * 4;
            float4 o;
            o.x = acc[i][jq * 4 + 0] + bi[n + 0] + bh[n + 0];
            o.y = acc[i][jq * 4 + 1] + bi[n + 1] + bh[n + 1];
            o.z = acc[i][jq * 4 + 2] + bi[n + 2] + bh[n + 2];
            o.w = acc[i][jq * 4 + 3] + bi[n + 3] + bh[n + 3];
            *(float4*)&C[(size_t)m * Gz + n] = o;
        }
    }
}

// -------- grid barrier (per-direction, monotonic counter) --------
__device__ __forceinline__ void bar_sync(unsigned* cnt, unsigned target) {
    __syncthreads();
    if (threadIdx.x == 0) {
        __threadfence();
        atomicAdd(cnt, 1u);
        unsigned v;
        do {
            asm volatile("ld.acquire.gpu.u32 %0, [%1];" : "=r"(v) : "l"(cnt) : "memory");
        } while (v < target);
    }
    __syncthreads();
}

__global__ void reset_bar() {
    if (threadIdx.x < 2) g_barcnt[threadIdx.x] = 0;
}

// -------- persistent bidirectional LSTM recurrence (one launch = 512 steps) --------
// grid = 128 CTAs: dir = bx&1, colblock cb = bx>>1 (64 blocks of 8 hidden units).
// W_hh rows for this CTA (32 rows = 4 gates x 8 units) live in SMEM for all steps.
// h ping-pongs via global (k-major [u][b]), c stays in registers.
#define SM_W  0
#define SM_H  16384
#define SM_G  32768
#define REC_SMEM_FLOATS (16384 + 16384 + 32 * 33)
#define REC_SMEM_BYTES  (REC_SMEM_FLOATS * 4)

__global__ __launch_bounds__(128) void lstm_rec(
    const float* __restrict__ Wf, const float* __restrict__ Wb,
    float* __restrict__ outbuf, int st_t, int st_b)
{
    extern __shared__ float sm[];
    float* w_s = sm + SM_W;     // [512 k][32 c]   c = gate*8 + q
    float* h_s = sm + SM_H;     // [512 k][32 b]
    float* g_s = sm + SM_G;     // [32 b][33]

    int dir = blockIdx.x & 1;
    int cb = blockIdx.x >> 1;
    int u0 = cb * 8;
    const float* W = dir ? Wb : Wf;
    const float* xg = dir ? g_xg1 : g_xg0;
    unsigned* cnt = &g_barcnt[dir];
    int tid = threadIdx.x;

    // ---- load this CTA's 32 W_hh rows into SMEM (once) ----
    {
        int c = tid >> 2, kq = tid & 3;
        const float* wrow = W + (size_t)((c >> 3) * Hz + u0 + (c & 7)) * Hz;
#pragma unroll 4
        for (int p = 0; p < 32; p++) {
            int k = p * 16 + kq * 4;
            float4 v = *(const float4*)&wrow[k];
            w_s[(k + 0) * 32 + c] = v.x;
            w_s[(k + 1) * 32 + c] = v.y;
            w_s[(k + 2) * 32 + c] = v.z;
            w_s[(k + 3) * 32 + c] = v.w;
        }
    }

    // ---- zero our slice of h parity-0, zero c (registers) ----
    {
        float* hz = g_hbuf[dir][0];
        hz[u0 * 32 + tid * 2 + 0] = 0.f;
        hz[u0 * 32 + tid * 2 + 1] = 0.f;
    }
    float creg[2] = {0.f, 0.f};

    bar_sync(cnt, 64u);   // init barrier

    int b0 = (tid >> 4) * 4;     // batch group (4)
    int c0 = (tid & 15) * 2;     // col pair

    for (int s = 0; s < Tz; s++) {
        int rb = s & 1;
        int wb = rb ^ 1;
        int t = dir ? (Tz - 1 - s) : s;
        const float* hp = g_hbuf[dir][rb];

        // stage h [512][32] into SMEM (L1-bypassing loads: must see other SMs' writes)
        for (int i = tid; i < 4096; i += 128) {
            float4 v = __ldcg((const float4*)hp + i);
            *(float4*)&h_s[i * 4] = v;
        }
        __syncthreads();

        // 32x32 gate-GEMM slice: acc[b][c] += h[k][b] * w[k][c]
        float acc[4][2] = {{0.f,0.f},{0.f,0.f},{0.f,0.f},{0.f,0.f}};
#pragma unroll 8
        for (int k = 0; k < Hz; k++) {
            float4 a = *(const float4*)&h_s[k * 32 + b0];
            float2 w2 = *(const float2*)&w_s[k * 32 + c0];
            acc[0][0] += a.x * w2.x;  acc[0][1] += a.x * w2.y;
            acc[1][0] += a.y * w2.x;  acc[1][1] += a.y * w2.y;
            acc[2][0] += a.z * w2.x;  acc[2][1] += a.z * w2.y;
            acc[3][0] += a.w * w2.x;  acc[3][1] += a.w * w2.y;
        }

#pragma unroll
        for (int i = 0; i < 4; i++) {
            g_s[(b0 + i) * 33 + c0 + 0] = acc[i][0];
            g_s[(b0 + i) * 33 + c0 + 1] = acc[i][1];
        }
        __syncthreads();

        // ---- gate nonlinearity + state update (2 (b,u) pairs per thread) ----
        float* hnew = g_hbuf[dir][wb];
        const float* xgt = xg + (size_t)t * Bz * Gz;
#pragma unroll
        for (int q = 0; q < 2; q++) {
            int pp = tid * 2 + q;
            int b = pp >> 3, ul = pp & 7;
            int u = u0 + ul;
            const float* xr = xgt + (size_t)b * Gz + u;
            float gi = g_s[b * 33 + 0  + ul] + xr[0 * Hz];
            float gf = g_s[b * 33 + 8  + ul] + xr[1 * Hz];
            float gg = g_s[b * 33 + 16 + ul] + xr[2 * Hz];
            float go = g_s[b * 33 + 24 + ul] + xr[3 * Hz];
            float iv = sigf(gi), fv = sigf(gf), gv = tanhf_(gg), ov = sigf(go);
            float cn = fv * creg[q] + iv * gv;
            float hn = ov * tanhf_(cn);
            creg[q] = cn;
            hnew[u * 32 + b] = hn;
            outbuf[(size_t)t * st_t + (size_t)b * st_b + dir * Hz + u] = hn;
        }

        bar_sync(cnt, 64u * (unsigned)(s + 2));
    }

    // ---- write final c to global ([b][u] layout for easy copy) ----
#pragma unroll
    for (int q = 0; q < 2; q++) {
        int pp = tid * 2 + q;
        int b = pp >> 3, u = u0 + (pp & 7);
        g_cbuf[dir][b * Hz + u] = creg[q];
    }
}

// -------- copy final h/c into h_n / c_n sections of d_out --------
__global__ void copy_state(float* __restrict__ dout, int layer) {
    int idx = blockIdx.x * 256 + threadIdx.x;   // 0..32767
    int d = idx >> 14;
    int r = idx & 16383;           // r = b*512 + u
    int b = r >> 9, u = r & 511;
    const size_t OUT = (size_t)Bz * Tz * 2 * Hz;
    dout[OUT + (size_t)(2 * layer + d) * (Bz * Hz) + r] = g_hbuf[d][0][u * 32 + b];
    dout[OUT + 4 * (size_t)(Bz * Hz) + (size_t)(2 * layer + d) * (Bz * Hz) + r] = g_cbuf[d][r];
}

extern "C" void kernel_launch(void* const* d_in, const int* in_sizes, int n_in,
                              void* d_out, int out_size)
{
    const float* x        = (const float*)d_in[0];
    const float* w_ih_l0  = (const float*)d_in[1];
    const float* w_hh_l0  = (const float*)d_in[2];
    const float* b_ih_l0  = (const float*)d_in[3];
    const float* b_hh_l0  = (const float*)d_in[4];
    const float* w_ih_l0r = (const float*)d_in[5];
    const float* w_hh_l0r = (const float*)d_in[6];
    const float* b_ih_l0r = (const float*)d_in[7];
    const float* b_hh_l0r = (const float*)d_in[8];
    const float* w_ih_l1  = (const float*)d_in[9];
    const float* w_hh_l1  = (const float*)d_in[10];
    const float* b_ih_l1  = (const float*)d_in[11];
    const float* b_hh_l1  = (const float*)d_in[12];
    const float* w_ih_l1r = (const float*)d_in[13];
    const float* w_hh_l1r = (const float*)d_in[14];
    const float* b_ih_l1r = (const float*)d_in[15];
    const float* b_hh_l1r = (const float*)d_in[16];
    float* out = (float*)d_out;

    void* p;
    float *xt, *y0;
    cudaGetSymbolAddress(&p, g_xt);   xt  = (float*)p;
    cudaGetSymbolAddress(&p, g_y0);   y0  = (float*)p;
    float *xg0, *xg1;
    cudaGetSymbolAddress(&p, g_xg0);  xg0 = (float*)p;
    cudaGetSymbolAddress(&p, g_xg1);  xg1 = (float*)p;

    cudaFuncSetAttribute(lstm_rec, cudaFuncAttributeMaxDynamicSharedMemorySize,
                         REC_SMEM_BYTES);

    // x [B,I,T] -> xt [T,B,I]
    transpose_x<<<dim3(Tz / 32, Iz / 32, Bz), dim3(32, 8)>>>(x);

    dim3 gg(Gz / 128, TB / 128);   // (16, 128)

    // ---- layer 0 ----
    gemm_xg<<<gg, 256>>>(xt, w_ih_l0,  b_ih_l0,  b_hh_l0,  xg0, Iz);
    gemm_xg<<<gg, 256>>>(xt, w_ih_l0r, b_ih_l0r, b_hh_l0r, xg1, Iz);
    reset_bar<<<1, 32>>>();
    lstm_rec<<<128, 128, REC_SMEM_BYTES>>>(w_hh_l0, w_hh_l0r, y0,
                                           Bz * 2 * Hz, 2 * Hz);
    copy_state<<<128, 256>>>(out, 0);

    // ---- layer 1 ----
    gemm_xg<<<gg, 256>>>(y0, w_ih_l1,  b_ih_l1,  b_hh_l1,  xg0, 2 * Hz);
    gemm_xg<<<gg, 256>>>(y0, w_ih_l1r, b_ih_l1r, b_hh_l1r, xg1, 2 * Hz);
    reset_bar<<<1, 32>>>();
    lstm_rec<<<128, 128, REC_SMEM_BYTES>>>(w_hh_l1, w_hh_l1r, out,
                                           2 * Hz, Tz * 2 * Hz);
    copy_state<<<128, 256>>>(out, 1);
}

// round 4
// speedup vs baseline: 1.1954x; 1.1954x over previous
#include <cuda_runtime.h>
#include <cstdint>

#define Tz 512
#define Bz 32
#define Iz 256
#define Hz 512
#define Gz 2048          // 4*H
#define TB (Tz*Bz)       // 16384

// -------- scratch (device globals; no runtime allocation) --------
__device__ float g_xt[(size_t)TB * Iz];        // x transposed to [T,B,I]
__device__ float g_xg0[(size_t)TB * Gz];       // fwd-dir input-gate projections
__device__ float g_xg1[(size_t)TB * Gz];       // bwd-dir input-gate projections
__device__ float g_y0[(size_t)TB * 2 * Hz];    // layer-0 output [T,B,2H]
__device__ float g_hbuf[2][2][Hz * Bz];        // [dir][parity][u*32+b]  (k-major!)
__device__ float g_cbuf[2][Bz * Hz];           // [dir][b*H+u]
__device__ unsigned g_barcnt[2];               // per-direction arrival counters

__device__ __forceinline__ float sigf(float x) { return 1.f / (1.f + __expf(-x)); }
__device__ __forceinline__ float tanhf_(float x) { return 2.f / (1.f + __expf(-2.f * x)) - 1.f; }

__device__ __forceinline__ uint32_t f2tf32(float f) {
    uint32_t r;
    asm("cvt.rna.tf32.f32 %0, %1;" : "=r"(r) : "f"(f));
    return r;
}

// mma.sync tf32 m16n8k8 (portable sm_80+ path; runs on Blackwell tensor pipe)
__device__ __forceinline__ void mma_tf32(float* c, const uint32_t* a,
                                         uint32_t b0, uint32_t b1) {
    asm volatile(
        "mma.sync.aligned.m16n8k8.row.col.f32.tf32.tf32.f32 "
        "{%0,%1,%2,%3}, {%4,%5,%6,%7}, {%8,%9}, {%0,%1,%2,%3};"
        : "+f"(c[0]), "+f"(c[1]), "+f"(c[2]), "+f"(c[3])
        : "r"(a[0]), "r"(a[1]), "r"(a[2]), "r"(a[3]), "r"(b0), "r"(b1));
}

// -------- transpose x [B,I,T] -> xt [T,B,I] --------
__global__ void transpose_x(const float* __restrict__ x) {
    __shared__ float tile[32][33];
    int b = blockIdx.z, i0 = blockIdx.y * 32, t0 = blockIdx.x * 32;
    int tx = threadIdx.x, ty = threadIdx.y;
#pragma unroll
    for (int r = ty; r < 32; r += 8)
        tile[r][tx] = x[(size_t)b * Iz * Tz + (size_t)(i0 + r) * Tz + t0 + tx];
    __syncthreads();
#pragma unroll
    for (int r = ty; r < 32; r += 8)
        g_xt[(size_t)(t0 + r) * Bz * Iz + (size_t)b * Iz + i0 + tx] = tile[tx][r];
}

// ======== tf32 mma.sync GEMM: C[M,Gz] = A[M,K] @ W[Gz,K]^T + bi + bh ========
// CTA tile 128x128, 8 warps of 32x64; K chunked by 32; A/B in SMEM as
// [row][36] fp32-width tf32 bits (conflict-free fragment loads).
__global__ __launch_bounds__(256) void gemm_xg_mma(
    const float* __restrict__ A, const float* __restrict__ W,
    const float* __restrict__ bi, const float* __restrict__ bh,
    float* __restrict__ C, int K)
{
    __shared__ uint32_t As[128 * 36];
    __shared__ uint32_t Bs[128 * 36];

    int tid = threadIdx.x;
    int wid = tid >> 5, lane = tid & 31;
    int gid = lane >> 2, tig = lane & 3;
    int n0 = blockIdx.x * 128, m0 = blockIdx.y * 128;
    int mwarp = (wid >> 1) * 32;     // 0,32,64,96
    int nwarp = (wid & 1) * 64;      // 0,64

    float c[2][8][4];
#pragma unroll
    for (int mt = 0; mt < 2; mt++)
#pragma unroll
        for (int nt = 0; nt < 8; nt++)
#pragma unroll
            for (int q = 0; q < 4; q++) c[mt][nt][q] = 0.f;

    for (int k0 = 0; k0 < K; k0 += 32) {
        // fill A tile: 128 rows x 32 k (1024 float4 / 256 threads = 4 each)
#pragma unroll
        for (int j = 0; j < 4; j++) {
            int i = tid + j * 256;
            int row = i >> 3, q = i & 7;
            float4 v = *(const float4*)&A[(size_t)(m0 + row) * K + k0 + q * 4];
            uint4 t;
            t.x = f2tf32(v.x); t.y = f2tf32(v.y); t.z = f2tf32(v.z); t.w = f2tf32(v.w);
            *(uint4*)&As[row * 36 + q * 4] = t;
        }
        // fill B tile (W rows n0..n0+127)
#pragma unroll
        for (int j = 0; j < 4; j++) {
            int i = tid + j * 256;
            int row = i >> 3, q = i & 7;
            float4 v = *(const float4*)&W[(size_t)(n0 + row) * K + k0 + q * 4];
            uint4 t;
            t.x = f2tf32(v.x); t.y = f2tf32(v.y); t.z = f2tf32(v.z); t.w = f2tf32(v.w);
            *(uint4*)&Bs[row * 36 + q * 4] = t;
        }
        __syncthreads();

#pragma unroll
        for (int kk = 0; kk < 32; kk += 8) {
            uint32_t a[2][4];
#pragma unroll
            for (int mt = 0; mt < 2; mt++) {
                int mrow = mwarp + mt * 16;
                a[mt][0] = As[(mrow + gid)     * 36 + kk + tig];
                a[mt][1] = As[(mrow + gid + 8) * 36 + kk + tig];
                a[mt][2] = As[(mrow + gid)     * 36 + kk + tig + 4];
                a[mt][3] = As[(mrow + gid + 8) * 36 + kk + tig + 4];
            }
#pragma unroll
            for (int nt = 0; nt < 8; nt++) {
                uint32_t b0 = Bs[(nwarp + nt * 8 + gid) * 36 + kk + tig];
                uint32_t b1 = Bs[(nwarp + nt * 8 + gid) * 36 + kk + tig + 4];
                mma_tf32(c[0][nt], a[0], b0, b1);
                mma_tf32(c[1][nt], a[1], b0, b1);
            }
        }
        __syncthreads();
    }

    // epilogue: c0,c1 -> (m, n..n+1); c2,c3 -> (m+8, n..n+1)
#pragma unroll
    for (int mt = 0; mt < 2; mt++) {
        int m = m0 + mwarp + mt * 16 + gid;
#pragma unroll
        for (int nt = 0; nt < 8; nt++) {
            int n = n0 + nwarp + nt * 8 + 2 * tig;
            float bs0 = bi[n] + bh[n];
            float bs1 = bi[n + 1] + bh[n + 1];
            float2 o0 = {c[mt][nt][0] + bs0, c[mt][nt][1] + bs1};
            float2 o1 = {c[mt][nt][2] + bs0, c[mt][nt][3] + bs1};
            *(float2*)&C[(size_t)m * Gz + n] = o0;
            *(float2*)&C[(size_t)(m + 8) * Gz + n] = o1;
        }
    }
}

// -------- grid barrier (per-direction, monotonic counter) --------
__device__ __forceinline__ void bar_sync(unsigned* cnt, unsigned target) {
    __syncthreads();
    if (threadIdx.x == 0) {
        __threadfence();
        atomicAdd(cnt, 1u);
        unsigned v;
        do {
            asm volatile("ld.acquire.gpu.u32 %0, [%1];" : "=r"(v) : "l"(cnt) : "memory");
        } while (v < target);
    }
    __syncthreads();
}

__global__ void reset_bar() {
    if (threadIdx.x < 2) g_barcnt[threadIdx.x] = 0;
}

// -------- persistent bidirectional LSTM recurrence (one launch = 512 steps) --------
#define SM_W  0
#define SM_H  16384
#define SM_G  32768
#define REC_SMEM_FLOATS (16384 + 16384 + 32 * 33)
#define REC_SMEM_BYTES  (REC_SMEM_FLOATS * 4)

__global__ __launch_bounds__(128) void lstm_rec(
    const float* __restrict__ Wf, const float* __restrict__ Wb,
    float* __restrict__ outbuf, int st_t, int st_b)
{
    extern __shared__ float sm[];
    float* w_s = sm + SM_W;     // [512 k][32 c]
    float* h_s = sm + SM_H;     // [512 k][32 b]
    float* g_s = sm + SM_G;     // [32 b][33]

    int dir = blockIdx.x & 1;
    int cb = blockIdx.x >> 1;
    int u0 = cb * 8;
    const float* W = dir ? Wb : Wf;
    const float* xg = dir ? g_xg1 : g_xg0;
    unsigned* cnt = &g_barcnt[dir];
    int tid = threadIdx.x;

    {
        int c = tid >> 2, kq = tid & 3;
        const float* wrow = W + (size_t)((c >> 3) * Hz + u0 + (c & 7)) * Hz;
#pragma unroll 4
        for (int p = 0; p < 32; p++) {
            int k = p * 16 + kq * 4;
            float4 v = *(const float4*)&wrow[k];
            w_s[(k + 0) * 32 + c] = v.x;
            w_s[(k + 1) * 32 + c] = v.y;
            w_s[(k + 2) * 32 + c] = v.z;
            w_s[(k + 3) * 32 + c] = v.w;
        }
    }

    {
        float* hz = g_hbuf[dir][0];
        hz[u0 * 32 + tid * 2 + 0] = 0.f;
        hz[u0 * 32 + tid * 2 + 1] = 0.f;
    }
    float creg[2] = {0.f, 0.f};

    bar_sync(cnt, 64u);

    int b0 = (tid >> 4) * 4;
    int c0 = (tid & 15) * 2;

    for (int s = 0; s < Tz; s++) {
        int rb = s & 1;
        int wb = rb ^ 1;
        int t = dir ? (Tz - 1 - s) : s;
        const float* hp = g_hbuf[dir][rb];

        for (int i = tid; i < 4096; i += 128) {
            float4 v = __ldcg((const float4*)hp + i);
            *(float4*)&h_s[i * 4] = v;
        }
        __syncthreads();

        float acc[4][2] = {{0.f,0.f},{0.f,0.f},{0.f,0.f},{0.f,0.f}};
#pragma unroll 8
        for (int k = 0; k < Hz; k++) {
            float4 a = *(const float4*)&h_s[k * 32 + b0];
            float2 w2 = *(const float2*)&w_s[k * 32 + c0];
            acc[0][0] += a.x * w2.x;  acc[0][1] += a.x * w2.y;
            acc[1][0] += a.y * w2.x;  acc[1][1] += a.y * w2.y;
            acc[2][0] += a.z * w2.x;  acc[2][1] += a.z * w2.y;
            acc[3][0] += a.w * w2.x;  acc[3][1] += a.w * w2.y;
        }

#pragma unroll
        for (int i = 0; i < 4; i++) {
            g_s[(b0 + i) * 33 + c0 + 0] = acc[i][0];
            g_s[(b0 + i) * 33 + c0 + 1] = acc[i][1];
        }
        __syncthreads();

        float* hnew = g_hbuf[dir][wb];
        const float* xgt = xg + (size_t)t * Bz * Gz;
#pragma unroll
        for (int q = 0; q < 2; q++) {
            int pp = tid * 2 + q;
            int b = pp >> 3, ul = pp & 7;
            int u = u0 + ul;
            const float* xr = xgt + (size_t)b * Gz + u;
            float gi = g_s[b * 33 + 0  + ul] + xr[0 * Hz];
            float gf = g_s[b * 33 + 8  + ul] + xr[1 * Hz];
            float gg = g_s[b * 33 + 16 + ul] + xr[2 * Hz];
            float go = g_s[b * 33 + 24 + ul] + xr[3 * Hz];
            float iv = sigf(gi), fv = sigf(gf), gv = tanhf_(gg), ov = sigf(go);
            float cn = fv * creg[q] + iv * gv;
            float hn = ov * tanhf_(cn);
            creg[q] = cn;
            hnew[u * 32 + b] = hn;
            outbuf[(size_t)t * st_t + (size_t)b * st_b + dir * Hz + u] = hn;
        }

        bar_sync(cnt, 64u * (unsigned)(s + 2));
    }

#pragma unroll
    for (int q = 0; q < 2; q++) {
        int pp = tid * 2 + q;
        int b = pp >> 3, u = u0 + (pp & 7);
        g_cbuf[dir][b * Hz + u] = creg[q];
    }
}

// -------- copy final h/c into h_n / c_n sections of d_out --------
__global__ void copy_state(float* __restrict__ dout, int layer) {
    int idx = blockIdx.x * 256 + threadIdx.x;   // 0..32767
    int d = idx >> 14;
    int r = idx & 16383;           // r = b*512 + u
    int b = r >> 9, u = r & 511;
    const size_t OUT = (size_t)Bz * Tz * 2 * Hz;
    dout[OUT + (size_t)(2 * layer + d) * (Bz * Hz) + r] = g_hbuf[d][0][u * 32 + b];
    dout[OUT + 4 * (size_t)(Bz * Hz) + (size_t)(2 * layer + d) * (Bz * Hz) + r] = g_cbuf[d][r];
}

extern "C" void kernel_launch(void* const* d_in, const int* in_sizes, int n_in,
                              void* d_out, int out_size)
{
    const float* x        = (const float*)d_in[0];
    const float* w_ih_l0  = (const float*)d_in[1];
    const float* w_hh_l0  = (const float*)d_in[2];
    const float* b_ih_l0  = (const float*)d_in[3];
    const float* b_hh_l0  = (const float*)d_in[4];
    const float* w_ih_l0r = (const float*)d_in[5];
    const float* w_hh_l0r = (const float*)d_in[6];
    const float* b_ih_l0r = (const float*)d_in[7];
    const float* b_hh_l0r = (const float*)d_in[8];
    const float* w_ih_l1  = (const float*)d_in[9];
    const float* w_hh_l1  = (const float*)d_in[10];
    const float* b_ih_l1  = (const float*)d_in[11];
    const float* b_hh_l1  = (const float*)d_in[12];
    const float* w_ih_l1r = (const float*)d_in[13];
    const float* w_hh_l1r = (const float*)d_in[14];
    const float* b_ih_l1r = (const float*)d_in[15];
    const float* b_hh_l1r = (const float*)d_in[16];
    float* out = (float*)d_out;

    void* p;
    float *xt, *y0, *xg0, *xg1;
    cudaGetSymbolAddress(&p, g_xt);   xt  = (float*)p;
    cudaGetSymbolAddress(&p, g_y0);   y0  = (float*)p;
    cudaGetSymbolAddress(&p, g_xg0);  xg0 = (float*)p;
    cudaGetSymbolAddress(&p, g_xg1);  xg1 = (float*)p;

    cudaFuncSetAttribute(lstm_rec, cudaFuncAttributeMaxDynamicSharedMemorySize,
                         REC_SMEM_BYTES);

    // x [B,I,T] -> xt [T,B,I]
    transpose_x<<<dim3(Tz / 32, Iz / 32, Bz), dim3(32, 8)>>>(x);

    dim3 gg(Gz / 128, TB / 128);   // (16, 128)

    // ---- layer 0 ----
    gemm_xg_mma<<<gg, 256>>>(xt, w_ih_l0,  b_ih_l0,  b_hh_l0,  xg0, Iz);
    gemm_xg_mma<<<gg, 256>>>(xt, w_ih_l0r, b_ih_l0r, b_hh_l0r, xg1, Iz);
    reset_bar<<<1, 32>>>();
    lstm_rec<<<128, 128, REC_SMEM_BYTES>>>(w_hh_l0, w_hh_l0r, y0,
                                           Bz * 2 * Hz, 2 * Hz);
    copy_state<<<128, 256>>>(out, 0);

    // ---- layer 1 ----
    gemm_xg_mma<<<gg, 256>>>(y0, w_ih_l1,  b_ih_l1,  b_hh_l1,  xg0, 2 * Hz);
    gemm_xg_mma<<<gg, 256>>>(y0, w_ih_l1r, b_ih_l1r, b_hh_l1r, xg1, 2 * Hz);
    reset_bar<<<1, 32>>>();
    lstm_rec<<<128, 128, REC_SMEM_BYTES>>>(w_hh_l1, w_hh_l1r, out,
                                           2 * Hz, Tz * 2 * Hz);
    copy_state<<<128, 256>>>(out, 1);
}